// round 7
// baseline (speedup 1.0000x reference)
#include <cuda_runtime.h>
#include <cuda_bf16.h>
#include <math.h>
#include <cstdint>

#define T_LEN 512
#define BSZ   256
#define DIM   512
#define HID   512
#define N4    (4 * HID)       /* 2048 */

// Scratch: input projections [T][B][4H].
__device__ float g_Y[268435456];               // 131072 * 2048
// bf16 hi/lo copies of X and W (W rows: gate*512 + r, gates f,i,o,a).
__device__ __nv_bfloat16 g_Xh[67108864];       // 131072 * 512
__device__ __nv_bfloat16 g_Xl[67108864];
__device__ __nv_bfloat16 g_Wh[1048576];        // 2048 * 512
__device__ __nv_bfloat16 g_Wl[1048576];
// Grid barrier state.
__device__ unsigned g_sync[64];

// ============================================================================
// helpers
// ============================================================================
__device__ __forceinline__ uint32_t smem_u32(const void* p) {
    uint32_t a;
    asm("{ .reg .u64 t; cvta.to.shared.u64 t, %1; cvt.u32.u64 %0, t; }"
        : "=r"(a) : "l"(p));
    return a;
}
__device__ __forceinline__ void ldsm_x4(uint32_t& r0, uint32_t& r1,
                                        uint32_t& r2, uint32_t& r3,
                                        uint32_t addr) {
    asm volatile("ldmatrix.sync.aligned.m8n8.x4.shared.b16 {%0,%1,%2,%3}, [%4];"
                 : "=r"(r0), "=r"(r1), "=r"(r2), "=r"(r3) : "r"(addr));
}
__device__ __forceinline__ void mma16816(float* c, const uint32_t* a,
                                         uint32_t b0, uint32_t b1) {
    asm volatile(
        "mma.sync.aligned.m16n8k16.row.col.f32.bf16.bf16.f32 "
        "{%0,%1,%2,%3}, {%4,%5,%6,%7}, {%8,%9}, {%0,%1,%2,%3};"
        : "+f"(c[0]), "+f"(c[1]), "+f"(c[2]), "+f"(c[3])
        : "r"(a[0]), "r"(a[1]), "r"(a[2]), "r"(a[3]), "r"(b0), "r"(b1));
}
#define CP_ASYNC16(dst, src) \
    asm volatile("cp.async.cg.shared.global [%0], [%1], 16;" \
                 :: "r"(dst), "l"(src) : "memory")
#define CP_COMMIT() asm volatile("cp.async.commit_group;" ::: "memory")
#define CP_WAIT(n)  asm volatile("cp.async.wait_group %0;" :: "n"(n) : "memory")

// packed f32x2 ops
__device__ __forceinline__ unsigned long long pack2(float x, float y) {
    unsigned long long r;
    asm("mov.b64 %0, {%1, %2};" : "=l"(r) : "f"(x), "f"(y));
    return r;
}
__device__ __forceinline__ void unpack2(unsigned long long v, float& x, float& y) {
    asm("mov.b64 {%0, %1}, %2;" : "=f"(x), "=f"(y) : "l"(v));
}
__device__ __forceinline__ unsigned long long fma2(
    unsigned long long a, unsigned long long b, unsigned long long c) {
    unsigned long long d;
    asm("fma.rn.f32x2 %0, %1, %2, %3;" : "=l"(d) : "l"(a), "l"(b), "l"(c));
    return d;
}

// fp32 -> bf16 hi/lo split, packed pairwise.
__device__ __forceinline__ void split2(float x, float y, uint32_t& hi, uint32_t& lo) {
    __nv_bfloat16 hx = __float2bfloat16(x);
    __nv_bfloat16 hy = __float2bfloat16(y);
    float rx = x - __bfloat162float(hx);
    float ry = y - __bfloat162float(hy);
    __nv_bfloat16 lx = __float2bfloat16(rx);
    __nv_bfloat16 ly = __float2bfloat16(ry);
    __nv_bfloat162 hp = __nv_bfloat162(hx, hy);
    __nv_bfloat162 lp = __nv_bfloat162(lx, ly);
    hi = *reinterpret_cast<uint32_t*>(&hp);
    lo = *reinterpret_cast<uint32_t*>(&lp);
}

// ============================================================================
// One-time conversion kernels.
// ============================================================================
__global__ __launch_bounds__(256) void convert_x(const float* __restrict__ X) {
    size_t i = (size_t)blockIdx.x * blockDim.x + threadIdx.x;   // per float4
    float4 v = reinterpret_cast<const float4*>(X)[i];
    uint32_t h0, h1, l0, l1;
    split2(v.x, v.y, h0, l0);
    split2(v.z, v.w, h1, l1);
    reinterpret_cast<uint2*>(g_Xh)[i] = make_uint2(h0, h1);
    reinterpret_cast<uint2*>(g_Xl)[i] = make_uint2(l0, l1);
}
__global__ __launch_bounds__(256) void convert_w(
    const float* __restrict__ Wf, const float* __restrict__ Wi,
    const float* __restrict__ Wo, const float* __restrict__ Wa) {
    size_t i = (size_t)blockIdx.x * blockDim.x + threadIdx.x;   // per float4
    int gate = (int)(i >> 16);                  // 65536 float4 per gate
    const float* W = (gate == 0) ? Wf : (gate == 1) ? Wi : (gate == 2) ? Wo : Wa;
    float4 v = reinterpret_cast<const float4*>(W)[i & 65535];
    uint32_t h0, h1, l0, l1;
    split2(v.x, v.y, h0, l0);
    split2(v.z, v.w, h1, l1);
    reinterpret_cast<uint2*>(g_Wh)[i] = make_uint2(h0, h1);
    reinterpret_cast<uint2*>(g_Wl)[i] = make_uint2(l0, l1);
}

// ============================================================================
// Tensor-core GEMM1 (bf16 hi/lo 3-term, fp32 acc), cp.async 2-stage pipeline.
// ============================================================================
__global__ __launch_bounds__(256, 1) void gemm_xproj_mma(
    const float* __restrict__ bf, const float* __restrict__ bi,
    const float* __restrict__ bo)
{
    extern __shared__ __align__(128) char smem[];
    const uint32_t sb = smem_u32(smem);

    const int tid  = threadIdx.x;
    const int lane = tid & 31;
    const int wid  = tid >> 5;
    const int wm   = wid >> 1;   // 0..3
    const int wn   = wid & 1;    // 0..1

    const int nTile = blockIdx.x;            // 0..15
    const int mBase = blockIdx.y * 128;
    const int gate  = nTile >> 2;
    const int rowG  = (nTile & 3) * 128;
    const float* bias = (gate == 0) ? bf : (gate == 1) ? bi : (gate == 2) ? bo : nullptr;

    const __nv_bfloat16* Ah = g_Xh + (size_t)mBase * DIM;
    const __nv_bfloat16* Al = g_Xl + (size_t)mBase * DIM;
    const __nv_bfloat16* Bh = g_Wh + (size_t)nTile * 128 * DIM;
    const __nv_bfloat16* Bl = g_Wl + (size_t)nTile * 128 * DIM;

    float c[2][8][4];
#pragma unroll
    for (int mf = 0; mf < 2; mf++)
#pragma unroll
        for (int nf = 0; nf < 8; nf++)
#pragma unroll
            for (int q = 0; q < 4; q++) c[mf][nf][q] = 0.f;

    auto stage = [&](int chunk, int s) {
        const int kb = chunk * 64;
        const uint32_t sOff = (uint32_t)s * 65536;
#pragma unroll
        for (int it = 0; it < 4; it++) {
            int idx = tid + it * 256;
            int row = idx >> 3;
            int ch  = idx & 7;
            uint32_t off = sOff + (uint32_t)row * 128 + ((ch ^ (row & 7)) << 4);
            const size_t g = (size_t)row * DIM + kb + ch * 8;
            CP_ASYNC16(sb + off,         Ah + g);
            CP_ASYNC16(sb + off + 16384, Al + g);
            CP_ASYNC16(sb + off + 32768, Bh + g);
            CP_ASYNC16(sb + off + 49152, Bl + g);
        }
        CP_COMMIT();
    };

    stage(0, 0);

    for (int chunk = 0; chunk < 8; chunk++) {
        if (chunk < 7) {
            stage(chunk + 1, (chunk + 1) & 1);
            CP_WAIT(1);
        } else {
            CP_WAIT(0);
        }
        __syncthreads();

        const uint32_t sOff = (uint32_t)(chunk & 1) * 65536;
        const uint32_t AH = sOff, AL = sOff + 16384, BH = sOff + 32768, BL = sOff + 49152;

#pragma unroll
        for (int ks = 0; ks < 4; ks++) {
            const int chv = ks * 2 + (lane >> 4);

            uint32_t ah[2][4], al[2][4];
#pragma unroll
            for (int mf = 0; mf < 2; mf++) {
                const int row = wm * 32 + mf * 16 + (lane & 15);
                const uint32_t addr =
                    sb + (uint32_t)row * 128 + (((chv ^ (row & 7))) << 4);
                ldsm_x4(ah[mf][0], ah[mf][1], ah[mf][2], ah[mf][3], addr + AH);
                ldsm_x4(al[mf][0], al[mf][1], al[mf][2], al[mf][3], addr + AL);
            }
            {
                uint32_t bh[4][4];
#pragma unroll
                for (int np = 0; np < 4; np++) {
                    const int row = wn * 64 + np * 16 + (lane & 15);
                    const uint32_t addr =
                        sb + BH + (uint32_t)row * 128 + (((chv ^ (row & 7))) << 4);
                    ldsm_x4(bh[np][0], bh[np][1], bh[np][2], bh[np][3], addr);
                }
#pragma unroll
                for (int mf = 0; mf < 2; mf++)
#pragma unroll
                    for (int nf = 0; nf < 8; nf++) {
                        const int np = nf >> 1, s = nf & 1;
                        mma16816(c[mf][nf], ah[mf], bh[np][s], bh[np][s + 2]);
                        mma16816(c[mf][nf], al[mf], bh[np][s], bh[np][s + 2]);
                    }
            }
            {
                uint32_t bl[4][4];
#pragma unroll
                for (int np = 0; np < 4; np++) {
                    const int row = wn * 64 + np * 16 + (lane & 15);
                    const uint32_t addr =
                        sb + BL + (uint32_t)row * 128 + (((chv ^ (row & 7))) << 4);
                    ldsm_x4(bl[np][0], bl[np][1], bl[np][2], bl[np][3], addr);
                }
#pragma unroll
                for (int mf = 0; mf < 2; mf++)
#pragma unroll
                    for (int nf = 0; nf < 8; nf++) {
                        const int np = nf >> 1, s = nf & 1;
                        mma16816(c[mf][nf], ah[mf], bl[np][s], bl[np][s + 2]);
                    }
            }
        }
        __syncthreads();
    }

    const int colBase = nTile * 128 + wn * 64 + (lane & 3) * 2;
    const int rBase   = mBase + wm * 32 + (lane >> 2);
#pragma unroll
    for (int nf = 0; nf < 8; nf++) {
        const int col = colBase + nf * 8;
        const int ln  = wn * 64 + nf * 8 + (lane & 3) * 2;
        float b0 = bias ? __ldg(bias + rowG + ln)     : 0.f;
        float b1 = bias ? __ldg(bias + rowG + ln + 1) : 0.f;
#pragma unroll
        for (int mf = 0; mf < 2; mf++) {
            const size_t r0 = (size_t)(rBase + mf * 16);
            float2 o0 = make_float2(c[mf][nf][0] + b0, c[mf][nf][1] + b1);
            float2 o1 = make_float2(c[mf][nf][2] + b0, c[mf][nf][3] + b1);
            *reinterpret_cast<float2*>(g_Y + r0 * N4 + col)       = o0;
            *reinterpret_cast<float2*>(g_Y + (r0 + 8) * N4 + col) = o1;
        }
    }
}

// ---------------------------------------------------------------------------
// Persistent recurrence, FFMA2 version.
// 128 blocks (16 n x 8 m tiles of 32x32), 256 threads (8 warps, warp = 4 n).
// smem: Wp[256 kp][32 n] u64 pairs (64KB) | Hp[256 kp][32 m] u64 pairs (64KB),
// Hp swizzled col = m ^ ((kp>>1)&31). c in regs. Y(t+1) prefetched pre-barrier.
// ---------------------------------------------------------------------------
__device__ __forceinline__ float sigf(float x) {
    return 1.f / (1.f + __expf(-x));
}
__device__ __forceinline__ float tanh_fast(float x) {
    return 2.f / (1.f + __expf(-2.f * x)) - 1.f;
}

__global__ __launch_bounds__(256, 1) void lstm_persistent(
    const float* __restrict__ Waa,
    const float* __restrict__ ba,
    float*       __restrict__ out,
    float*       __restrict__ hn)
{
    extern __shared__ __align__(16) unsigned long long smu[];
    unsigned long long* Wp = smu;            // 8192 u64
    unsigned long long* Hp = smu + 8192;     // 8192 u64

    const int tid  = threadIdx.x;
    const int lane = tid & 31;
    const int w    = tid >> 5;            // 0..7
    const int nBase = (blockIdx.x & 15) * 32;
    const int mBase = (blockIdx.x >> 4) * 32;
    const int n0 = w * 4;                 // warp's 4 n-cols
    const int m  = lane;
    const unsigned nblk = gridDim.x;

    // One-time: Waa[nBase+nl][k] -> k-pair layout Wp[kp][nl].
#pragma unroll
    for (int i = 0; i < 16; i++) {
        int idx = tid + i * 256;          // 0..4095
        int nl = idx & 31;
        int k4 = idx >> 5;                // 0..127
        float4 v = *reinterpret_cast<const float4*>(
            Waa + (size_t)(nBase + nl) * HID + k4 * 4);
        Wp[(k4 * 2)     * 32 + nl] = pack2(v.x, v.y);
        Wp[(k4 * 2 + 1) * 32 + nl] = pack2(v.z, v.w);
    }

    float ban[4];
#pragma unroll
    for (int j = 0; j < 4; j++) ban[j] = ba[nBase + n0 + j];

    float c[4];
#pragma unroll
    for (int j = 0; j < 4; j++) c[j] = 0.f;

    __syncthreads();

    volatile unsigned* genp = &g_sync[32];

    // Gate pre-activation prefetch for step t (independent of h).
    const float* yr0 = g_Y + ((size_t)mBase + m) * N4 + nBase + n0;
    float pf[4], pi[4], po[4], pa[4];
    *reinterpret_cast<float4*>(pf) = *reinterpret_cast<const float4*>(yr0);
    *reinterpret_cast<float4*>(pi) = *reinterpret_cast<const float4*>(yr0 + HID);
    *reinterpret_cast<float4*>(po) = *reinterpret_cast<const float4*>(yr0 + 2 * HID);
    *reinterpret_cast<float4*>(pa) = *reinterpret_cast<const float4*>(yr0 + 3 * HID);

    for (int t = 0; t < T_LEN; t++) {
        unsigned long long acc[4];
#pragma unroll
        for (int j = 0; j < 4; j++) acc[j] = pack2(0.f, 0.f);

        if (t > 0) {
            // Stage h(t-1): global [m][k] -> pair layout Hp[kp][m^((kp>>1)&31)].
            const float* hsrc = out + ((size_t)(t - 1) * BSZ + mBase) * HID;
#pragma unroll
            for (int i = 0; i < 16; i++) {
                int idx = tid + i * 256;      // 0..4095
                int mm = idx >> 7;            // 0..31
                int k4 = idx & 127;           // coalesced within warp
                float4 v = *reinterpret_cast<const float4*>(
                    hsrc + (size_t)mm * HID + k4 * 4);
                int col = mm ^ (k4 & 31);     // (kp>>1)&31 == k4&31 for both pairs
                Hp[(k4 * 2)     * 32 + col] = pack2(v.x, v.y);
                Hp[(k4 * 2 + 1) * 32 + col] = pack2(v.z, v.w);
            }
            __syncthreads();

            // acc[n] (even,odd k halves) += h[m][k] * Waa[n][k]
#pragma unroll 8
            for (int kp = 0; kp < 256; kp++) {
                const int col = m ^ ((kp >> 1) & 31);
                unsigned long long h2 = Hp[kp * 32 + col];
                ulonglong2 wa = *reinterpret_cast<const ulonglong2*>(
                    Wp + kp * 32 + n0);
                ulonglong2 wb = *reinterpret_cast<const ulonglong2*>(
                    Wp + kp * 32 + n0 + 2);
                acc[0] = fma2(h2, wa.x, acc[0]);
                acc[1] = fma2(h2, wa.y, acc[1]);
                acc[2] = fma2(h2, wb.x, acc[2]);
                acc[3] = fma2(h2, wb.y, acc[3]);
            }
        }

        // Gates (Y was prefetched last iteration).
        float hv[4];
#pragma unroll
        for (int j = 0; j < 4; j++) {
            float e0, e1;
            unpack2(acc[j], e0, e1);
            float a  = e0 + e1 + ban[j];
            float ft = sigf(pf[j] + a);
            float it = sigf(pi[j] + a);
            float ot = sigf(po[j] + a);
            float g  = tanh_fast(pa[j] + a);
            c[j] = ft * c[j] + it * g;
            hv[j] = ot * tanh_fast(c[j]);
        }
        float* hout = out + ((size_t)t * BSZ + mBase + m) * HID + nBase + n0;
        *reinterpret_cast<float4*>(hout) =
            make_float4(hv[0], hv[1], hv[2], hv[3]);
        if (hn && t == T_LEN - 1)
            *reinterpret_cast<float4*>(hn + (size_t)(mBase + m) * HID + nBase + n0) =
                make_float4(hv[0], hv[1], hv[2], hv[3]);

        if (t < T_LEN - 1) {
            // Prefetch Y for t+1 (hidden under the grid barrier).
            const float* yr = yr0 + (size_t)(t + 1) * BSZ * N4;
            *reinterpret_cast<float4*>(pf) = *reinterpret_cast<const float4*>(yr);
            *reinterpret_cast<float4*>(pi) = *reinterpret_cast<const float4*>(yr + HID);
            *reinterpret_cast<float4*>(po) = *reinterpret_cast<const float4*>(yr + 2 * HID);
            *reinterpret_cast<float4*>(pa) = *reinterpret_cast<const float4*>(yr + 3 * HID);

            __syncthreads();
            if (tid == 0) {
                unsigned gen = *genp;
                __threadfence();
                if (atomicAdd(&g_sync[0], 1u) == nblk - 1) {
                    atomicExch(&g_sync[0], 0u);
                    __threadfence();
                    *genp = gen + 1;
                } else {
                    while (*genp == gen) { }
                }
                __threadfence();
            }
            __syncthreads();
        }
    }
}

// ---------------------------------------------------------------------------
extern "C" void kernel_launch(void* const* d_in, const int* in_sizes, int n_in,
                              void* d_out, int out_size)
{
    (void)in_sizes; (void)n_in;
    const float* X   = (const float*)d_in[0];
    const float* Wf  = (const float*)d_in[1];
    const float* Wi  = (const float*)d_in[2];
    const float* Wo  = (const float*)d_in[3];
    const float* Wa  = (const float*)d_in[4];
    const float* Waa = (const float*)d_in[5];
    const float* bf  = (const float*)d_in[6];
    const float* bi  = (const float*)d_in[7];
    const float* bo  = (const float*)d_in[8];
    const float* ba  = (const float*)d_in[9];
    float* out = (float*)d_out;

    const int gemm_smem = 131072;   // 128 KB
    const int rec_smem  = 131072;   // 128 KB (Wp 64K + Hp 64K)
    static bool attr_set = false;
    if (!attr_set) {
        cudaFuncSetAttribute(gemm_xproj_mma,
                             cudaFuncAttributeMaxDynamicSharedMemorySize,
                             gemm_smem);
        cudaFuncSetAttribute(lstm_persistent,
                             cudaFuncAttributeMaxDynamicSharedMemorySize,
                             rec_smem);
        attr_set = true;
    }

    convert_x<<<65536, 256>>>(X);
    convert_w<<<1024, 256>>>(Wf, Wi, Wo, Wa);

    dim3 g1(16, 1024);
    gemm_xproj_mma<<<g1, 256, gemm_smem>>>(bf, bi, bo);

    const size_t step_elems = (size_t)BSZ * HID;
    const size_t outs_elems = (size_t)T_LEN * step_elems;
    float* hn_ptr = ((size_t)out_size >= outs_elems + step_elems)
                        ? out + outs_elems : nullptr;

    lstm_persistent<<<128, 256, rec_smem>>>(Waa, ba, out, hn_ptr);
}

// round 8
// speedup vs baseline: 1.7215x; 1.7215x over previous
#include <cuda_runtime.h>
#include <cuda_fp16.h>
#include <math.h>
#include <cstdint>

#define T_LEN 512
#define BSZ   256
#define DIM   512
#define HID   512
#define N4    (4 * HID)       /* 2048 */

// Scratch: input projections [T][B][4H].
__device__ float g_Y[268435456];          // 131072 * 2048
// fp16 copies of X and W (W rows: gate*512 + r, gates f,i,o,a).
__device__ __half g_Xf[67108864];         // 131072 * 512
__device__ __half g_Wf[1048576];          // 2048 * 512
// Grid barrier state.
__device__ unsigned g_sync[64];

// ============================================================================
// helpers
// ============================================================================
__device__ __forceinline__ uint32_t smem_u32(const void* p) {
    uint32_t a;
    asm("{ .reg .u64 t; cvta.to.shared.u64 t, %1; cvt.u32.u64 %0, t; }"
        : "=r"(a) : "l"(p));
    return a;
}
__device__ __forceinline__ void ldsm_x4(uint32_t& r0, uint32_t& r1,
                                        uint32_t& r2, uint32_t& r3,
                                        uint32_t addr) {
    asm volatile("ldmatrix.sync.aligned.m8n8.x4.shared.b16 {%0,%1,%2,%3}, [%4];"
                 : "=r"(r0), "=r"(r1), "=r"(r2), "=r"(r3) : "r"(addr));
}
__device__ __forceinline__ void mma16816(float* c, const uint32_t* a,
                                         uint32_t b0, uint32_t b1) {
    asm volatile(
        "mma.sync.aligned.m16n8k16.row.col.f32.f16.f16.f32 "
        "{%0,%1,%2,%3}, {%4,%5,%6,%7}, {%8,%9}, {%0,%1,%2,%3};"
        : "+f"(c[0]), "+f"(c[1]), "+f"(c[2]), "+f"(c[3])
        : "r"(a[0]), "r"(a[1]), "r"(a[2]), "r"(a[3]), "r"(b0), "r"(b1));
}
#define CP_ASYNC16(dst, src) \
    asm volatile("cp.async.cg.shared.global [%0], [%1], 16;" \
                 :: "r"(dst), "l"(src) : "memory")
#define CP_COMMIT() asm volatile("cp.async.commit_group;" ::: "memory")
#define CP_WAIT(n)  asm volatile("cp.async.wait_group %0;" :: "n"(n) : "memory")

// ============================================================================
// One-time fp32 -> fp16 conversion kernels.
// ============================================================================
__global__ __launch_bounds__(256) void convert_x_h(const float* __restrict__ X) {
    size_t i = (size_t)blockIdx.x * blockDim.x + threadIdx.x;   // per float4
    float4 v = reinterpret_cast<const float4*>(X)[i];
    __half2 a = __floats2half2_rn(v.x, v.y);
    __half2 b = __floats2half2_rn(v.z, v.w);
    reinterpret_cast<uint2*>(g_Xf)[i] =
        make_uint2(*reinterpret_cast<uint32_t*>(&a),
                   *reinterpret_cast<uint32_t*>(&b));
}
__global__ __launch_bounds__(256) void convert_w_h(
    const float* __restrict__ Wf, const float* __restrict__ Wi,
    const float* __restrict__ Wo, const float* __restrict__ Wa) {
    size_t i = (size_t)blockIdx.x * blockDim.x + threadIdx.x;   // per float4
    int gate = (int)(i >> 16);                  // 65536 float4 per gate
    const float* W = (gate == 0) ? Wf : (gate == 1) ? Wi : (gate == 2) ? Wo : Wa;
    float4 v = reinterpret_cast<const float4*>(W)[i & 65535];
    __half2 a = __floats2half2_rn(v.x, v.y);
    __half2 b = __floats2half2_rn(v.z, v.w);
    reinterpret_cast<uint2*>(g_Wf)[i] =
        make_uint2(*reinterpret_cast<uint32_t*>(&a),
                   *reinterpret_cast<uint32_t*>(&b));
}

// ============================================================================
// GEMM1 via fp16 mma.sync (1 term, fp32 acc), cp.async 2-stage pipeline.
// CTA 128x128, K chunk 64, 256 thr (8 warps = 4m x 2n, warp tile 32x64).
// Stage (32KB): A|B @ 16KB, XOR-swizzled 16B chunks. 2 stages = 64KB smem.
// ============================================================================
__global__ __launch_bounds__(256, 2) void gemm_xproj_mma(
    const float* __restrict__ bf, const float* __restrict__ bi,
    const float* __restrict__ bo)
{
    extern __shared__ __align__(128) char smem[];
    const uint32_t sb = smem_u32(smem);

    const int tid  = threadIdx.x;
    const int lane = tid & 31;
    const int wid  = tid >> 5;
    const int wm   = wid >> 1;   // 0..3
    const int wn   = wid & 1;    // 0..1

    const int nTile = blockIdx.x;            // 0..15
    const int mBase = blockIdx.y * 128;
    const int gate  = nTile >> 2;
    const int rowG  = (nTile & 3) * 128;
    const float* bias = (gate == 0) ? bf : (gate == 1) ? bi : (gate == 2) ? bo : nullptr;

    const __half* A = g_Xf + (size_t)mBase * DIM;
    const __half* B = g_Wf + (size_t)nTile * 128 * DIM;

    float c[2][8][4];
#pragma unroll
    for (int mf = 0; mf < 2; mf++)
#pragma unroll
        for (int nf = 0; nf < 8; nf++)
#pragma unroll
            for (int q = 0; q < 4; q++) c[mf][nf][q] = 0.f;

    // stage chunk -> buffer s: 8 cp.async 16B per thread (4 A + 4 B).
    auto stage = [&](int chunk, int s) {
        const int kb = chunk * 64;
        const uint32_t sOff = (uint32_t)s * 32768;
#pragma unroll
        for (int it = 0; it < 4; it++) {
            int idx = tid + it * 256;
            int row = idx >> 3;           // 0..127
            int ch  = idx & 7;            // 16B chunk in row
            uint32_t off = sOff + (uint32_t)row * 128 + ((ch ^ (row & 7)) << 4);
            const size_t g = (size_t)row * DIM + kb + ch * 8;
            CP_ASYNC16(sb + off,         A + g);
            CP_ASYNC16(sb + off + 16384, B + g);
        }
        CP_COMMIT();
    };

    stage(0, 0);

    for (int chunk = 0; chunk < 8; chunk++) {
        if (chunk < 7) {
            stage(chunk + 1, (chunk + 1) & 1);
            CP_WAIT(1);
        } else {
            CP_WAIT(0);
        }
        __syncthreads();

        const uint32_t sOff = (uint32_t)(chunk & 1) * 32768;
        const uint32_t AS = sOff, BS = sOff + 16384;

#pragma unroll
        for (int ks = 0; ks < 4; ks++) {
            const int chv = ks * 2 + (lane >> 4);

            uint32_t a[2][4];
#pragma unroll
            for (int mf = 0; mf < 2; mf++) {
                const int row = wm * 32 + mf * 16 + (lane & 15);
                const uint32_t addr =
                    sb + AS + (uint32_t)row * 128 + (((chv ^ (row & 7))) << 4);
                ldsm_x4(a[mf][0], a[mf][1], a[mf][2], a[mf][3], addr);
            }
            uint32_t b[4][4];
#pragma unroll
            for (int np = 0; np < 4; np++) {
                const int row = wn * 64 + np * 16 + (lane & 15);
                const uint32_t addr =
                    sb + BS + (uint32_t)row * 128 + (((chv ^ (row & 7))) << 4);
                ldsm_x4(b[np][0], b[np][1], b[np][2], b[np][3], addr);
            }
#pragma unroll
            for (int mf = 0; mf < 2; mf++)
#pragma unroll
                for (int nf = 0; nf < 8; nf++) {
                    const int np = nf >> 1, s = nf & 1;
                    mma16816(c[mf][nf], a[mf], b[np][s], b[np][s + 2]);
                }
        }
        __syncthreads();
    }

    // Epilogue: add bias, write fp32 to g_Y.
    const int colBase = nTile * 128 + wn * 64 + (lane & 3) * 2;
    const int rBase   = mBase + wm * 32 + (lane >> 2);
#pragma unroll
    for (int nf = 0; nf < 8; nf++) {
        const int col = colBase + nf * 8;
        const int ln  = wn * 64 + nf * 8 + (lane & 3) * 2;
        float b0 = bias ? __ldg(bias + rowG + ln)     : 0.f;
        float b1 = bias ? __ldg(bias + rowG + ln + 1) : 0.f;
#pragma unroll
        for (int mf = 0; mf < 2; mf++) {
            const size_t r0 = (size_t)(rBase + mf * 16);
            float2 o0 = make_float2(c[mf][nf][0] + b0, c[mf][nf][1] + b1);
            float2 o1 = make_float2(c[mf][nf][2] + b0, c[mf][nf][3] + b1);
            *reinterpret_cast<float2*>(g_Y + r0 * N4 + col)       = o0;
            *reinterpret_cast<float2*>(g_Y + (r0 + 8) * N4 + col) = o1;
        }
    }
}

// ---------------------------------------------------------------------------
// Persistent recurrence kernel (round-6 version, verbatim).
// ---------------------------------------------------------------------------
__device__ __forceinline__ float sigf(float x) {
    return 1.f / (1.f + __expf(-x));
}
__device__ __forceinline__ float tanh_fast(float x) {
    return 2.f / (1.f + __expf(-2.f * x)) - 1.f;
}

__global__ __launch_bounds__(128, 1) void lstm_persistent(
    const float* __restrict__ Waa,
    const float* __restrict__ ba,
    float*       __restrict__ out,
    float*       __restrict__ hn)
{
    extern __shared__ float sm[];
    float* Ws = sm;
    float* hs = sm + 16384;

    const int tid  = threadIdx.x;
    const int lane = tid & 31;
    const int w    = tid >> 5;
    const int nBase = (blockIdx.x & 15) * 32;
    const int mBase = (blockIdx.x >> 4) * 32;
    const int n0 = w * 8;
    const int m  = lane;
    const unsigned nblk = gridDim.x;

    for (int e = tid; e < 4096; e += 128) {
        int nl = e & 31;
        int k4 = e >> 5;
        float4 v = *reinterpret_cast<const float4*>(
            Waa + (size_t)(nBase + nl) * HID + k4 * 4);
        Ws[(k4 * 4 + 0) * 32 + nl] = v.x;
        Ws[(k4 * 4 + 1) * 32 + nl] = v.y;
        Ws[(k4 * 4 + 2) * 32 + nl] = v.z;
        Ws[(k4 * 4 + 3) * 32 + nl] = v.w;
    }

    float ban[8];
#pragma unroll
    for (int j = 0; j < 8; j++) ban[j] = ba[nBase + n0 + j];

    float c[8];
#pragma unroll
    for (int j = 0; j < 8; j++) c[j] = 0.f;

    __syncthreads();

    volatile unsigned* genp = &g_sync[32];

    for (int t = 0; t < T_LEN; t++) {
        float acc[8];
#pragma unroll
        for (int j = 0; j < 8; j++) acc[j] = 0.f;

        if (t > 0) {
            const float* hsrc = out + ((size_t)(t - 1) * BSZ + mBase) * HID;
#pragma unroll
            for (int i = 0; i < 32; i++) {
                int e  = tid + i * 128;
                int mm = e >> 7;
                int k4 = e & 127;
                float4 v = *reinterpret_cast<const float4*>(
                    hsrc + (size_t)mm * HID + k4 * 4);
                int col = mm ^ (k4 & 31);
                hs[(k4 * 4 + 0) * 32 + col] = v.x;
                hs[(k4 * 4 + 1) * 32 + col] = v.y;
                hs[(k4 * 4 + 2) * 32 + col] = v.z;
                hs[(k4 * 4 + 3) * 32 + col] = v.w;
            }
            __syncthreads();

#pragma unroll 4
            for (int kq = 0; kq < 128; kq++) {
                const int col = m ^ (kq & 31);
                const float* hp = hs + kq * 128 + col;
                const float* wp = Ws + kq * 128 + n0;
#pragma unroll
                for (int j = 0; j < 4; j++) {
                    float a = hp[j * 32];
                    float4 b0 = *reinterpret_cast<const float4*>(wp + j * 32);
                    float4 b1 = *reinterpret_cast<const float4*>(wp + j * 32 + 4);
                    acc[0] = fmaf(a, b0.x, acc[0]);
                    acc[1] = fmaf(a, b0.y, acc[1]);
                    acc[2] = fmaf(a, b0.z, acc[2]);
                    acc[3] = fmaf(a, b0.w, acc[3]);
                    acc[4] = fmaf(a, b1.x, acc[4]);
                    acc[5] = fmaf(a, b1.y, acc[5]);
                    acc[6] = fmaf(a, b1.z, acc[6]);
                    acc[7] = fmaf(a, b1.w, acc[7]);
                }
            }
        }

        const float* yr = g_Y + ((size_t)t * BSZ + mBase + m) * N4 + nBase + n0;
        float* hout = out + ((size_t)t * BSZ + mBase + m) * HID + nBase + n0;
#pragma unroll
        for (int q = 0; q < 2; q++) {
            float4 xf = *reinterpret_cast<const float4*>(yr + q * 4);
            float4 xi = *reinterpret_cast<const float4*>(yr + HID + q * 4);
            float4 xo = *reinterpret_cast<const float4*>(yr + 2 * HID + q * 4);
            float4 xa = *reinterpret_cast<const float4*>(yr + 3 * HID + q * 4);
            float xfv[4] = {xf.x, xf.y, xf.z, xf.w};
            float xiv[4] = {xi.x, xi.y, xi.z, xi.w};
            float xov[4] = {xo.x, xo.y, xo.z, xo.w};
            float xav[4] = {xa.x, xa.y, xa.z, xa.w};
            float hv[4];
#pragma unroll
            for (int j = 0; j < 4; j++) {
                int o = q * 4 + j;
                float a  = acc[o] + ban[o];
                float ft = sigf(xfv[j] + a);
                float it = sigf(xiv[j] + a);
                float ot = sigf(xov[j] + a);
                float g  = tanh_fast(xav[j] + a);
                c[o] = ft * c[o] + it * g;
                hv[j] = ot * tanh_fast(c[o]);
            }
            float4 ho = make_float4(hv[0], hv[1], hv[2], hv[3]);
            *reinterpret_cast<float4*>(hout + q * 4) = ho;
            if (hn && t == T_LEN - 1)
                *reinterpret_cast<float4*>(
                    hn + (size_t)(mBase + m) * HID + nBase + n0 + q * 4) = ho;
        }

        if (t < T_LEN - 1) {
            __syncthreads();
            if (tid == 0) {
                unsigned gen = *genp;
                __threadfence();
                if (atomicAdd(&g_sync[0], 1u) == nblk - 1) {
                    atomicExch(&g_sync[0], 0u);
                    __threadfence();
                    *genp = gen + 1;
                } else {
                    while (*genp == gen) { }
                }
                __threadfence();
            }
            __syncthreads();
        }
    }
}

// ---------------------------------------------------------------------------
extern "C" void kernel_launch(void* const* d_in, const int* in_sizes, int n_in,
                              void* d_out, int out_size)
{
    (void)in_sizes; (void)n_in;
    const float* X   = (const float*)d_in[0];
    const float* Wf  = (const float*)d_in[1];
    const float* Wi  = (const float*)d_in[2];
    const float* Wo  = (const float*)d_in[3];
    const float* Wa  = (const float*)d_in[4];
    const float* Waa = (const float*)d_in[5];
    const float* bf  = (const float*)d_in[6];
    const float* bi  = (const float*)d_in[7];
    const float* bo  = (const float*)d_in[8];
    const float* ba  = (const float*)d_in[9];
    float* out = (float*)d_out;

    const int gemm_smem = 65536;                              // 64 KB (2 stages)
    const int rec_smem  = 2 * 512 * 32 * (int)sizeof(float);  // 128 KB
    static bool attr_set = false;
    if (!attr_set) {
        cudaFuncSetAttribute(gemm_xproj_mma,
                             cudaFuncAttributeMaxDynamicSharedMemorySize,
                             gemm_smem);
        cudaFuncSetAttribute(lstm_persistent,
                             cudaFuncAttributeMaxDynamicSharedMemorySize,
                             rec_smem);
        attr_set = true;
    }

    // One-time fp16 conversion.
    convert_x_h<<<65536, 256>>>(X);                 // 131072*512/4 float4
    convert_w_h<<<1024, 256>>>(Wf, Wi, Wo, Wa);     // 2048*512/4 float4

    dim3 g1(16, 1024);
    gemm_xproj_mma<<<g1, 256, gemm_smem>>>(bf, bi, bo);

    const size_t step_elems = (size_t)BSZ * HID;
    const size_t outs_elems = (size_t)T_LEN * step_elems;
    float* hn_ptr = ((size_t)out_size >= outs_elems + step_elems)
                        ? out + outs_elems : nullptr;

    lstm_persistent<<<128, 128, rec_smem>>>(Waa, ba, out, hn_ptr);
}

// round 9
// speedup vs baseline: 3.1319x; 1.8192x over previous
#include <cuda_runtime.h>
#include <cuda_fp16.h>
#include <math.h>
#include <cstdint>

#define T_LEN 512
#define BSZ   256
#define DIM   512
#define HID   512
#define N4    (4 * HID)       /* 2048 */

// Scratch: input projections [T][B][4H].
__device__ float g_Y[268435456];          // 131072 * 2048
// fp16 copies of X and W (W rows: gate*512 + r, gates f,i,o,a).
__device__ __half g_Xf[67108864];         // 131072 * 512
__device__ __half g_Wf[1048576];          // 2048 * 512
// Double-buffered fp16 h state [2][256][512].
__device__ __half g_h16[262144];
// Grid barrier state.
__device__ unsigned g_sync[64];

// ============================================================================
// helpers
// ============================================================================
__device__ __forceinline__ uint32_t smem_u32(const void* p) {
    uint32_t a;
    asm("{ .reg .u64 t; cvta.to.shared.u64 t, %1; cvt.u32.u64 %0, t; }"
        : "=r"(a) : "l"(p));
    return a;
}
__device__ __forceinline__ void ldsm_x4(uint32_t& r0, uint32_t& r1,
                                        uint32_t& r2, uint32_t& r3,
                                        uint32_t addr) {
    asm volatile("ldmatrix.sync.aligned.m8n8.x4.shared.b16 {%0,%1,%2,%3}, [%4];"
                 : "=r"(r0), "=r"(r1), "=r"(r2), "=r"(r3) : "r"(addr));
}
__device__ __forceinline__ void mma16816(float* c, const uint32_t* a,
                                         uint32_t b0, uint32_t b1) {
    asm volatile(
        "mma.sync.aligned.m16n8k16.row.col.f32.f16.f16.f32 "
        "{%0,%1,%2,%3}, {%4,%5,%6,%7}, {%8,%9}, {%0,%1,%2,%3};"
        : "+f"(c[0]), "+f"(c[1]), "+f"(c[2]), "+f"(c[3])
        : "r"(a[0]), "r"(a[1]), "r"(a[2]), "r"(a[3]), "r"(b0), "r"(b1));
}
#define CP_ASYNC16(dst, src) \
    asm volatile("cp.async.cg.shared.global [%0], [%1], 16;" \
                 :: "r"(dst), "l"(src) : "memory")
#define CP_COMMIT() asm volatile("cp.async.commit_group;" ::: "memory")
#define CP_WAIT(n)  asm volatile("cp.async.wait_group %0;" :: "n"(n) : "memory")

// ============================================================================
// One-time fp32 -> fp16 conversion kernels.
// ============================================================================
__global__ __launch_bounds__(256) void convert_x_h(const float* __restrict__ X) {
    size_t i = (size_t)blockIdx.x * blockDim.x + threadIdx.x;   // per float4
    float4 v = reinterpret_cast<const float4*>(X)[i];
    __half2 a = __floats2half2_rn(v.x, v.y);
    __half2 b = __floats2half2_rn(v.z, v.w);
    reinterpret_cast<uint2*>(g_Xf)[i] =
        make_uint2(*reinterpret_cast<uint32_t*>(&a),
                   *reinterpret_cast<uint32_t*>(&b));
}
__global__ __launch_bounds__(256) void convert_w_h(
    const float* __restrict__ Wf, const float* __restrict__ Wi,
    const float* __restrict__ Wo, const float* __restrict__ Wa) {
    size_t i = (size_t)blockIdx.x * blockDim.x + threadIdx.x;   // per float4
    int gate = (int)(i >> 16);                  // 65536 float4 per gate
    const float* W = (gate == 0) ? Wf : (gate == 1) ? Wi : (gate == 2) ? Wo : Wa;
    float4 v = reinterpret_cast<const float4*>(W)[i & 65535];
    __half2 a = __floats2half2_rn(v.x, v.y);
    __half2 b = __floats2half2_rn(v.z, v.w);
    reinterpret_cast<uint2*>(g_Wf)[i] =
        make_uint2(*reinterpret_cast<uint32_t*>(&a),
                   *reinterpret_cast<uint32_t*>(&b));
}

// ============================================================================
// GEMM1 via fp16 mma.sync (1 term, fp32 acc), cp.async 2-stage pipeline.
// (round-8 version, verbatim)
// ============================================================================
__global__ __launch_bounds__(256, 2) void gemm_xproj_mma(
    const float* __restrict__ bf, const float* __restrict__ bi,
    const float* __restrict__ bo)
{
    extern __shared__ __align__(128) char smem[];
    const uint32_t sb = smem_u32(smem);

    const int tid  = threadIdx.x;
    const int lane = tid & 31;
    const int wid  = tid >> 5;
    const int wm   = wid >> 1;
    const int wn   = wid & 1;

    const int nTile = blockIdx.x;
    const int mBase = blockIdx.y * 128;
    const int gate  = nTile >> 2;
    const int rowG  = (nTile & 3) * 128;
    const float* bias = (gate == 0) ? bf : (gate == 1) ? bi : (gate == 2) ? bo : nullptr;

    const __half* A = g_Xf + (size_t)mBase * DIM;
    const __half* B = g_Wf + (size_t)nTile * 128 * DIM;

    float c[2][8][4];
#pragma unroll
    for (int mf = 0; mf < 2; mf++)
#pragma unroll
        for (int nf = 0; nf < 8; nf++)
#pragma unroll
            for (int q = 0; q < 4; q++) c[mf][nf][q] = 0.f;

    auto stage = [&](int chunk, int s) {
        const int kb = chunk * 64;
        const uint32_t sOff = (uint32_t)s * 32768;
#pragma unroll
        for (int it = 0; it < 4; it++) {
            int idx = tid + it * 256;
            int row = idx >> 3;
            int ch  = idx & 7;
            uint32_t off = sOff + (uint32_t)row * 128 + ((ch ^ (row & 7)) << 4);
            const size_t g = (size_t)row * DIM + kb + ch * 8;
            CP_ASYNC16(sb + off,         A + g);
            CP_ASYNC16(sb + off + 16384, B + g);
        }
        CP_COMMIT();
    };

    stage(0, 0);

    for (int chunk = 0; chunk < 8; chunk++) {
        if (chunk < 7) {
            stage(chunk + 1, (chunk + 1) & 1);
            CP_WAIT(1);
        } else {
            CP_WAIT(0);
        }
        __syncthreads();

        const uint32_t sOff = (uint32_t)(chunk & 1) * 32768;
        const uint32_t AS = sOff, BS = sOff + 16384;

#pragma unroll
        for (int ks = 0; ks < 4; ks++) {
            const int chv = ks * 2 + (lane >> 4);

            uint32_t a[2][4];
#pragma unroll
            for (int mf = 0; mf < 2; mf++) {
                const int row = wm * 32 + mf * 16 + (lane & 15);
                const uint32_t addr =
                    sb + AS + (uint32_t)row * 128 + (((chv ^ (row & 7))) << 4);
                ldsm_x4(a[mf][0], a[mf][1], a[mf][2], a[mf][3], addr);
            }
            uint32_t b[4][4];
#pragma unroll
            for (int np = 0; np < 4; np++) {
                const int row = wn * 64 + np * 16 + (lane & 15);
                const uint32_t addr =
                    sb + BS + (uint32_t)row * 128 + (((chv ^ (row & 7))) << 4);
                ldsm_x4(b[np][0], b[np][1], b[np][2], b[np][3], addr);
            }
#pragma unroll
            for (int mf = 0; mf < 2; mf++)
#pragma unroll
                for (int nf = 0; nf < 8; nf++) {
                    const int np = nf >> 1, s = nf & 1;
                    mma16816(c[mf][nf], a[mf], b[np][s], b[np][s + 2]);
                }
        }
        __syncthreads();
    }

    const int colBase = nTile * 128 + wn * 64 + (lane & 3) * 2;
    const int rBase   = mBase + wm * 32 + (lane >> 2);
#pragma unroll
    for (int nf = 0; nf < 8; nf++) {
        const int col = colBase + nf * 8;
        const int ln  = wn * 64 + nf * 8 + (lane & 3) * 2;
        float b0 = bias ? __ldg(bias + rowG + ln)     : 0.f;
        float b1 = bias ? __ldg(bias + rowG + ln + 1) : 0.f;
#pragma unroll
        for (int mf = 0; mf < 2; mf++) {
            const size_t r0 = (size_t)(rBase + mf * 16);
            float2 o0 = make_float2(c[mf][nf][0] + b0, c[mf][nf][1] + b1);
            float2 o1 = make_float2(c[mf][nf][2] + b0, c[mf][nf][3] + b1);
            *reinterpret_cast<float2*>(g_Y + r0 * N4 + col)       = o0;
            *reinterpret_cast<float2*>(g_Y + (r0 + 8) * N4 + col) = o1;
        }
    }
}

// ============================================================================
// Persistent tensor-core recurrence.
// 128 blocks = 16 mTiles(16) x 8 nTiles(64), 256 threads (8 warps = 8 n-sub).
// Warp tile 16m x 8n, K=512 in k32 steps, W_aa as fp16 hi/lo (2-term).
// smem: Wh[64][512]f16 (64KB) | Wl (64KB) | Hs[16][512]f16 (16KB).
// h passed between steps via double-buffered g_h16; c in registers.
// ============================================================================
__device__ __forceinline__ float sigf(float x) {
    return 1.f / (1.f + __expf(-x));
}
__device__ __forceinline__ float tanh_fast(float x) {
    return 2.f / (1.f + __expf(-2.f * x)) - 1.f;
}

__global__ __launch_bounds__(256, 1) void lstm_persistent_tc(
    const float* __restrict__ Waa,
    const float* __restrict__ ba,
    float*       __restrict__ out,
    float*       __restrict__ hn)
{
    extern __shared__ __align__(128) char sm[];
    const uint32_t sb   = smem_u32(sm);
    const uint32_t sbWh = sb;
    const uint32_t sbWl = sb + 65536;
    const uint32_t sbH  = sb + 131072;

    const int tid  = threadIdx.x;
    const int lane = tid & 31;
    const int wid  = tid >> 5;                 // 0..7: n-subtile
    const int m0 = (blockIdx.x >> 3) * 16;     // batch rows
    const int n0 = (blockIdx.x & 7) * 64;      // hidden cols
    const unsigned nblk = gridDim.x;

    // --- one-time: Waa[n0+n][k] -> smem hi/lo fp16, swizzled 16B chunks ---
#pragma unroll
    for (int i = 0; i < 16; i++) {
        int idx = tid + i * 256;          // n(0..63) x chunk(0..63)
        int n = idx >> 6;
        int c = idx & 63;
        const float* src = Waa + (size_t)(n0 + n) * HID + c * 8;
        float4 v0 = *reinterpret_cast<const float4*>(src);
        float4 v1 = *reinterpret_cast<const float4*>(src + 4);
        float xs[8] = {v0.x, v0.y, v0.z, v0.w, v1.x, v1.y, v1.z, v1.w};
        __half2 hh[4], ll[4];
#pragma unroll
        for (int q = 0; q < 4; q++) {
            __half h0 = __float2half_rn(xs[q * 2]);
            __half h1 = __float2half_rn(xs[q * 2 + 1]);
            __half l0 = __float2half_rn(xs[q * 2]     - __half2float(h0));
            __half l1 = __float2half_rn(xs[q * 2 + 1] - __half2float(h1));
            hh[q] = __halves2half2(h0, h1);
            ll[q] = __halves2half2(l0, l1);
        }
        uint32_t off = (uint32_t)n * 1024 + ((c ^ (n & 7)) << 4);
        *reinterpret_cast<uint4*>(sm + off)         = *reinterpret_cast<uint4*>(hh);
        *reinterpret_cast<uint4*>(sm + 65536 + off) = *reinterpret_cast<uint4*>(ll);
    }

    // Per-thread output coordinates (mma c-frag layout).
    const int nn  = n0 + wid * 8 + (lane & 3) * 2;
    const int mr0 = m0 + (lane >> 2);
    const int mr1 = mr0 + 8;
    const float bav0 = ba[nn];
    const float bav1 = ba[nn + 1];

    float cc[4];
#pragma unroll
    for (int j = 0; j < 4; j++) cc[j] = 0.f;

    // ldsm row/addr components (loop-invariant).
    const int rA = (lane & 7) + ((lane >> 3) & 1) * 8;      // A row 0..15
    const int rB = wid * 8 + (lane & 7);                    // B row 0..63
    const uint32_t aRow = sbH  + (uint32_t)rA * 1024;
    const uint32_t bRowH = sbWh + (uint32_t)rB * 1024;
    const uint32_t bRowL = sbWl + (uint32_t)rB * 1024;
    const int swA = rA & 7, swB = rB & 7;

    __syncthreads();

    volatile unsigned* genp = &g_sync[32];

    // Y prefetch for t=0.
    float2 pf[2][4];
    {
        const float* yb = g_Y;
#pragma unroll
        for (int g = 0; g < 4; g++) {
            pf[0][g] = *reinterpret_cast<const float2*>(
                yb + (size_t)mr0 * N4 + g * HID + nn);
            pf[1][g] = *reinterpret_cast<const float2*>(
                yb + (size_t)mr1 * N4 + g * HID + nn);
        }
    }

    for (int t = 0; t < T_LEN; t++) {
        float acc[4] = {0.f, 0.f, 0.f, 0.f};

        if (t > 0) {
            // Stage h(t-1) fp16 tile from g_h16 buf[(t-1)&1] into Hs.
            const __half* hsrc = g_h16 + (size_t)((t - 1) & 1) * 131072
                                 + (size_t)m0 * HID;
#pragma unroll
            for (int i = 0; i < 4; i++) {
                int idx = tid + i * 256;      // row(0..15) x chunk(0..63)
                int r = idx >> 6;
                int c = idx & 63;
                uint4 v = *reinterpret_cast<const uint4*>(
                    hsrc + (size_t)r * HID + c * 8);
                *reinterpret_cast<uint4*>(
                    sm + 131072 + (uint32_t)r * 1024 + ((c ^ (r & 7)) << 4)) = v;
            }
            __syncthreads();

#pragma unroll 4
            for (int k0 = 0; k0 < 512; k0 += 32) {
                const int cb = k0 >> 3;
                const int chA = cb + (lane >> 4);
                const int chB = cb + (lane >> 3);
                uint32_t a0[4], a1[4], bh[4], bl[4];
                ldsm_x4(a0[0], a0[1], a0[2], a0[3],
                        aRow + ((chA ^ swA) << 4));
                ldsm_x4(a1[0], a1[1], a1[2], a1[3],
                        aRow + (((chA + 2) ^ swA) << 4));
                ldsm_x4(bh[0], bh[1], bh[2], bh[3],
                        bRowH + ((chB ^ swB) << 4));
                ldsm_x4(bl[0], bl[1], bl[2], bl[3],
                        bRowL + ((chB ^ swB) << 4));
                mma16816(acc, a0, bh[0], bh[1]);
                mma16816(acc, a0, bl[0], bl[1]);
                mma16816(acc, a1, bh[2], bh[3]);
                mma16816(acc, a1, bl[2], bl[3]);
            }
            __syncthreads();   // Hs reusable next step
        }

        // Gates + state update (c in regs).
        float hv[4];
#pragma unroll
        for (int r = 0; r < 2; r++) {
            float a0 = acc[r * 2 + 0] + bav0;
            float a1 = acc[r * 2 + 1] + bav1;
            float f0 = sigf(pf[r][0].x + a0), f1 = sigf(pf[r][0].y + a1);
            float i0 = sigf(pf[r][1].x + a0), i1 = sigf(pf[r][1].y + a1);
            float o0 = sigf(pf[r][2].x + a0), o1 = sigf(pf[r][2].y + a1);
            float g0 = tanh_fast(pf[r][3].x + a0);
            float g1 = tanh_fast(pf[r][3].y + a1);
            cc[r * 2 + 0] = f0 * cc[r * 2 + 0] + i0 * g0;
            cc[r * 2 + 1] = f1 * cc[r * 2 + 1] + i1 * g1;
            hv[r * 2 + 0] = o0 * tanh_fast(cc[r * 2 + 0]);
            hv[r * 2 + 1] = o1 * tanh_fast(cc[r * 2 + 1]);
        }

        // Store h: fp32 to out, fp16 to g_h16 buf[t&1].
        {
            float* ob = out + ((size_t)t * BSZ) * HID;
            *reinterpret_cast<float2*>(ob + (size_t)mr0 * HID + nn) =
                make_float2(hv[0], hv[1]);
            *reinterpret_cast<float2*>(ob + (size_t)mr1 * HID + nn) =
                make_float2(hv[2], hv[3]);
            __half* hb = g_h16 + (size_t)(t & 1) * 131072;
            *reinterpret_cast<__half2*>(hb + (size_t)mr0 * HID + nn) =
                __floats2half2_rn(hv[0], hv[1]);
            *reinterpret_cast<__half2*>(hb + (size_t)mr1 * HID + nn) =
                __floats2half2_rn(hv[2], hv[3]);
            if (hn && t == T_LEN - 1) {
                *reinterpret_cast<float2*>(hn + (size_t)mr0 * HID + nn) =
                    make_float2(hv[0], hv[1]);
                *reinterpret_cast<float2*>(hn + (size_t)mr1 * HID + nn) =
                    make_float2(hv[2], hv[3]);
            }
        }

        if (t < T_LEN - 1) {
            // Prefetch Y for t+1 (independent of h; hidden under barrier).
            const float* yb = g_Y + (size_t)(t + 1) * BSZ * N4;
#pragma unroll
            for (int g = 0; g < 4; g++) {
                pf[0][g] = *reinterpret_cast<const float2*>(
                    yb + (size_t)mr0 * N4 + g * HID + nn);
                pf[1][g] = *reinterpret_cast<const float2*>(
                    yb + (size_t)mr1 * N4 + g * HID + nn);
            }

            __syncthreads();
            if (tid == 0) {
                unsigned gen = *genp;
                __threadfence();
                if (atomicAdd(&g_sync[0], 1u) == nblk - 1) {
                    atomicExch(&g_sync[0], 0u);
                    __threadfence();
                    *genp = gen + 1;
                } else {
                    while (*genp == gen) { }
                }
                __threadfence();
            }
            __syncthreads();
        }
    }
}

// ---------------------------------------------------------------------------
extern "C" void kernel_launch(void* const* d_in, const int* in_sizes, int n_in,
                              void* d_out, int out_size)
{
    (void)in_sizes; (void)n_in;
    const float* X   = (const float*)d_in[0];
    const float* Wf  = (const float*)d_in[1];
    const float* Wi  = (const float*)d_in[2];
    const float* Wo  = (const float*)d_in[3];
    const float* Wa  = (const float*)d_in[4];
    const float* Waa = (const float*)d_in[5];
    const float* bf  = (const float*)d_in[6];
    const float* bi  = (const float*)d_in[7];
    const float* bo  = (const float*)d_in[8];
    const float* ba  = (const float*)d_in[9];
    float* out = (float*)d_out;

    const int gemm_smem = 65536;    // 64 KB
    const int rec_smem  = 147456;   // 64+64+16 KB
    static bool attr_set = false;
    if (!attr_set) {
        cudaFuncSetAttribute(gemm_xproj_mma,
                             cudaFuncAttributeMaxDynamicSharedMemorySize,
                             gemm_smem);
        cudaFuncSetAttribute(lstm_persistent_tc,
                             cudaFuncAttributeMaxDynamicSharedMemorySize,
                             rec_smem);
        attr_set = true;
    }

    convert_x_h<<<65536, 256>>>(X);
    convert_w_h<<<1024, 256>>>(Wf, Wi, Wo, Wa);

    dim3 g1(16, 1024);
    gemm_xproj_mma<<<g1, 256, gemm_smem>>>(bf, bi, bo);

    const size_t step_elems = (size_t)BSZ * HID;
    const size_t outs_elems = (size_t)T_LEN * step_elems;
    float* hn_ptr = ((size_t)out_size >= outs_elems + step_elems)
                        ? out + outs_elems : nullptr;

    lstm_persistent_tc<<<128, 256, rec_smem>>>(Waa, ba, out, hn_ptr);
}